// round 17
// baseline (speedup 1.0000x reference)
#include <cuda_runtime.h>
#include <cuda_fp16.h>
#include <math.h>
#include <stdint.h>

// Problem dims (fixed by the dataset)
#define DD    192
#define HDIM  12
#define SEQ   8192
#define BATCH 16
#define NROWS (BATCH * SEQ)
#define WELTS (DD * DD)         // 36864 elements per weight

// ---------------- scratch (static device globals) -------------------------
__device__ __half g_qh[(size_t)NROWS * DD];     // q (pre-scaled) fp16
__device__ __half g_kh[(size_t)NROWS * DD];     // k fp16
__device__ __half g_vh[(size_t)NROWS * DD];     // v fp16
__device__ __half g_xh[(size_t)NROWS * DD];     // x as fp16
__device__ __half g_ctxh[(size_t)NROWS * DD];   // attention context fp16
__device__ float  g_hf[(size_t)NROWS * DD];     // pre-LN h (fp32)
__device__ __half g_wh[(size_t)4 * WELTS];      // Wq,Wk,Wv,Wo as fp16

// ---------------- helpers --------------------------------------------------
__device__ __forceinline__ uint32_t pack_h2(__half a, __half b) {
    return (uint32_t)__half_as_ushort(a) | ((uint32_t)__half_as_ushort(b) << 16);
}

// fp16 m16n8k16 mma, fp32 accumulate
__device__ __forceinline__ void mma16(float* c, const uint32_t* a, const uint32_t* b) {
    asm volatile(
        "mma.sync.aligned.m16n8k16.row.col.f32.f16.f16.f32 "
        "{%0,%1,%2,%3}, {%4,%5,%6,%7}, {%8,%9}, {%0,%1,%2,%3};"
        : "+f"(c[0]), "+f"(c[1]), "+f"(c[2]), "+f"(c[3])
        : "r"(a[0]), "r"(a[1]), "r"(a[2]), "r"(a[3]), "r"(b[0]), "r"(b[1]));
}

// ldmatrix: 4x 8x8 b16 tiles, per-lane addresses
__device__ __forceinline__ void ldsm4(uint32_t& r0, uint32_t& r1,
                                      uint32_t& r2, uint32_t& r3, uint32_t addr) {
    asm volatile("ldmatrix.sync.aligned.m8n8.x4.shared.b16 {%0,%1,%2,%3}, [%4];"
                 : "=r"(r0), "=r"(r1), "=r"(r2), "=r"(r3) : "r"(addr));
}

// ---------------- prep: convert weights / activations to fp16 --------------
__global__ __launch_bounds__(256)
void cvt_weights(const float* __restrict__ Wq, const float* __restrict__ Wk,
                 const float* __restrict__ Wv, const float* __restrict__ Wo)
{
    int f = blockIdx.x * 256 + threadIdx.x;     // float4 index across 4 weights
    int w  = f / (WELTS / 4);
    int e4 = (f - w * (WELTS / 4)) * 4;
    const float* W = (w == 0) ? Wq : (w == 1) ? Wk : (w == 2) ? Wv : Wo;
    float4 a = *(const float4*)&W[e4];
    uint2 hp;
    hp.x = pack_h2(__float2half_rn(a.x), __float2half_rn(a.y));
    hp.y = pack_h2(__float2half_rn(a.z), __float2half_rn(a.w));
    *(uint2*)&g_wh[(size_t)w * WELTS + e4] = hp;
}

__global__ __launch_bounds__(256)
void cvt_x(const float* __restrict__ x)
{
    size_t f = (size_t)blockIdx.x * 256 + threadIdx.x;   // float4 index
    float4 a = ((const float4*)x)[f];
    uint2 hp;
    hp.x = pack_h2(__float2half_rn(a.x), __float2half_rn(a.y));
    hp.y = pack_h2(__float2half_rn(a.z), __float2half_rn(a.w));
    ((uint2*)g_xh)[f] = hp;
}

// ---------------- GEMM: fp16, BM=64 full-K tiles, 4 CTAs/SM ----------------
// out[seg][r, c] = (sum_k A[r,k] * W[seg][c,k] + bias[seg][c]) * scale[seg]
//                  (+ res[r,c] if res);  fp16 or fp32 output per out_half.
#define BM 64
#define BN 64
#define PADA 100                   // uint32 (fp16-pair) row stride: 96 + 4 pad
#define SM_A 0
#define SM_B (BM * PADA)           // 6400 words
#define GEMM_SMEM ((BM * PADA + BN * PADA) * 4)   // 51200 bytes

struct GemmArgs {
    int          plane[3];  // plane index in g_wh
    const float* bias[3];
    void*        out[3];
    float        scale[3];
    const float* res;
    int          out_half;  // 1: fp16 packed output, 0: fp32
};

__global__ __launch_bounds__(256, 4)
void gemm_fp16(const __half* __restrict__ Abase, GemmArgs args)
{
    extern __shared__ uint32_t smem[];

    const int col0g = blockIdx.x * BN;
    const int seg   = col0g / DD;
    const int lc0   = col0g - seg * DD;
    const int row0  = blockIdx.y * BM;

    const uint4* __restrict__ A4 = (const uint4*)Abase;            // 24 uint4/row
    const uint4* __restrict__ W4 =
        (const uint4*)(g_wh + (size_t)args.plane[seg] * WELTS);

    const int tid  = threadIdx.x;
    const int lane = tid & 31;
    const int warp = tid >> 5;
    const int wm   = (warp & 1) * 32;   // 2 warps in m (64 rows)
    const int wn   = (warp >> 1) * 16;  // 4 warps in n (64 cols)
    const int g    = lane >> 2;
    const int t    = lane & 3;

    const uint32_t smem_base = (uint32_t)__cvta_generic_to_shared(smem);

    // per-lane ldmatrix geometry (word units)
    const int arow  = wm + (lane & 15);
    const int aksel = (lane >> 4) * 4;
    const int brow  = wn + (lane & 7) + ((lane >> 4) << 3);
    const int bksel = ((lane >> 3) & 1) * 4;

    float acc[2][2][4];
    #pragma unroll
    for (int i = 0; i < 2; i++)
        #pragma unroll
        for (int j = 0; j < 2; j++)
            #pragma unroll
            for (int c = 0; c < 4; c++) acc[i][j][c] = 0.f;

    // ---- stage the FULL K=192 tile once (A: 1536 uint4, B: 1536 uint4) ----
    #pragma unroll
    for (int i = 0; i < 6; i++) {
        int idx = tid + i * 256;
        int m = idx / 24, q = idx - m * 24;
        *(uint4*)&smem[SM_A + m * PADA + q * 4] =
            A4[(size_t)(row0 + m) * 24 + q];
    }
    #pragma unroll
    for (int i = 0; i < 6; i++) {
        int idx = tid + i * 256;
        int n = idx / 24, q = idx - n * 24;
        *(uint4*)&smem[SM_B + n * PADA + q * 4] =
            W4[(size_t)(lc0 + n) * 24 + q];
    }
    __syncthreads();

    // ---- 12 uninterrupted ks-steps of pure LDSM + MMA ----------------------
    #pragma unroll
    for (int ks = 0; ks < 12; ks++) {
        const int kpb = ks * 8;
        uint32_t ah[2][4];
        #pragma unroll
        for (int mt = 0; mt < 2; mt++) {
            uint32_t aaddr = smem_base +
                (uint32_t)(SM_A + (arow + mt * 16) * PADA + kpb + aksel) * 4;
            ldsm4(ah[mt][0], ah[mt][1], ah[mt][2], ah[mt][3], aaddr);
        }
        uint32_t bh[2][2];
        {
            uint32_t baddr = smem_base +
                (uint32_t)(SM_B + brow * PADA + kpb + bksel) * 4;
            ldsm4(bh[0][0], bh[0][1], bh[1][0], bh[1][1], baddr);
        }
        #pragma unroll
        for (int mt = 0; mt < 2; mt++)
            #pragma unroll
            for (int nt = 0; nt < 2; nt++)
                mma16(acc[mt][nt], ah[mt], bh[nt]);
    }

    // ---- epilogue ----------------------------------------------------------
    const float scale = args.scale[seg];
    const float* const bias = args.bias[seg];
    const float* const res  = args.res;

    #pragma unroll
    for (int mt = 0; mt < 2; mt++) {
        #pragma unroll
        for (int nt = 0; nt < 2; nt++) {
            int row = row0 + wm + mt * 16 + g;
            int col = lc0 + wn + nt * 8 + t * 2;
            float b0 = bias[col], b1 = bias[col + 1];
            #pragma unroll
            for (int half = 0; half < 2; half++) {
                int r = row + half * 8;
                float v0 = (acc[mt][nt][half * 2 + 0] + b0) * scale;
                float v1 = (acc[mt][nt][half * 2 + 1] + b1) * scale;
                if (res != nullptr) {
                    const float2 rv = *(const float2*)&res[(size_t)r * DD + col];
                    v0 += rv.x; v1 += rv.y;
                }
                if (args.out_half) {
                    __half* outp = (__half*)args.out[seg];
                    *(uint32_t*)&outp[(size_t)r * DD + col] =
                        pack_h2(__float2half_rn(v0), __float2half_rn(v1));
                } else {
                    float* outp = (float*)args.out[seg];
                    float2 o; o.x = v0; o.y = v1;
                    *(float2*)&outp[(size_t)r * DD + col] = o;
                }
            }
        }
    }
}

// ---------------- banded attention: window d in [-2, 2], fp16 I/O ----------
#define TS 16
#define KVROWS (TS + 4)

__global__ __launch_bounds__(256)
void band_attn(const float* __restrict__ mask0)
{
    __shared__ __half ks[KVROWS * DD];   // 7680 B
    __shared__ __half vs[KVROWS * DD];
    __shared__ float  msk[KVROWS];

    const int chunk = blockIdx.x;
    const int b  = chunk / (SEQ / TS);
    const int s0 = (chunk % (SEQ / TS)) * TS;
    const int tid = threadIdx.x;

    for (int i4 = tid; i4 < KVROWS * 24; i4 += 256) {
        int r = i4 / 24;
        int c = i4 % 24;
        int s = s0 - 2 + r;
        uint4 kv = make_uint4(0, 0, 0, 0), vv = make_uint4(0, 0, 0, 0);
        if (s >= 0 && s < SEQ) {
            size_t off = (size_t)(b * SEQ + s) * DD + c * 8;
            kv = *(const uint4*)&g_kh[off];
            vv = *(const uint4*)&g_vh[off];
        }
        *(uint4*)&ks[r * DD + c * 8] = kv;
        *(uint4*)&vs[r * DD + c * 8] = vv;
    }
    if (tid < KVROWS) {
        int s = s0 - 2 + tid;
        msk[tid] = (s >= 0 && s < SEQ) ? mask0[b * SEQ + s] : 0.f;
    }
    __syncthreads();

    const int sl = tid >> 4;
    const int h  = tid & 15;
    const int s  = s0 + sl;

    float q[HDIM];
    {
        const __half2* qp = (const __half2*)&g_qh[(size_t)(b * SEQ + s) * DD + h * HDIM];
        #pragma unroll
        for (int j = 0; j < 6; j++) {
            float2 f = __half22float2(qp[j]);
            q[2*j] = f.x; q[2*j+1] = f.y;
        }
    }

    const float NEG  = -3.402823466e38f;
    const float NINF = __int_as_float(0xff800000);

    float sc[5];
    #pragma unroll
    for (int d = 0; d < 5; d++) {
        int r = sl + d;
        int skey = s + d - 2;
        const __half2* kp = (const __half2*)&ks[r * DD + h * HDIM];
        float dot = 0.f;
        #pragma unroll
        for (int j = 0; j < 6; j++) {
            float2 kf = __half22float2(kp[j]);
            dot += q[2*j] * kf.x + q[2*j+1] * kf.y;
        }
        float fm = (msk[r] != 0.f) ? NEG : 0.f;
        sc[d] = (skey >= 0 && skey < SEQ) ? (dot + fm) : NINF;
    }

    float mx = sc[0];
    #pragma unroll
    for (int d = 1; d < 5; d++) mx = fmaxf(mx, sc[d]);
    float e[5], sum = 0.f;
    #pragma unroll
    for (int d = 0; d < 5; d++) { e[d] = expf(sc[d] - mx); sum += e[d]; }
    float inv = 1.f / sum;
    bool index_masked = (msk[sl + 2] < 0.f);

    float c[HDIM] = {};
    #pragma unroll
    for (int d = 0; d < 5; d++) {
        float p = index_masked ? 0.f : e[d] * inv;
        const __half2* vp = (const __half2*)&vs[(sl + d) * DD + h * HDIM];
        #pragma unroll
        for (int j = 0; j < 6; j++) {
            float2 vf = __half22float2(vp[j]);
            c[2*j]   += p * vf.x;
            c[2*j+1] += p * vf.y;
        }
    }

    size_t base = (size_t)(b * SEQ + s) * DD + h * HDIM;
    uint32_t* oc = (uint32_t*)(g_ctxh + base);
    #pragma unroll
    for (int j = 0; j < 6; j++)
        oc[j] = pack_h2(__float2half_rn(c[2*j]), __float2half_rn(c[2*j+1]));
}

// ---------------- LayerNorm over the last dim (192), warp per row ----------
__global__ __launch_bounds__(256)
void layernorm(const float* __restrict__ ln_g, const float* __restrict__ ln_b,
               float* __restrict__ out)
{
    const int row  = blockIdx.x * 8 + (threadIdx.x >> 5);
    const int lane = threadIdx.x & 31;

    const float* hp = &g_hf[(size_t)row * DD];
    float h[6];
    float sum = 0.f;
    #pragma unroll
    for (int j = 0; j < 6; j++) { h[j] = hp[lane + j * 32]; sum += h[j]; }
    #pragma unroll
    for (int o = 16; o > 0; o >>= 1) sum += __shfl_xor_sync(0xffffffffu, sum, o);
    float mu = sum * (1.f / 192.f);

    float s2 = 0.f;
    #pragma unroll
    for (int j = 0; j < 6; j++) { float d = h[j] - mu; s2 += d * d; }
    #pragma unroll
    for (int o = 16; o > 0; o >>= 1) s2 += __shfl_xor_sync(0xffffffffu, s2, o);
    float invstd = rsqrtf(s2 * (1.f / 192.f) + 1e-12f);

    float* op = &out[(size_t)row * DD];
    #pragma unroll
    for (int j = 0; j < 6; j++) {
        int cc = lane + j * 32;
        op[cc] = (h[j] - mu) * invstd * ln_g[cc] + ln_b[cc];
    }
}

// ---------------- launch ---------------------------------------------------
extern "C" void kernel_launch(void* const* d_in, const int* in_sizes, int n_in,
                              void* d_out, int out_size)
{
    const float* x     = (const float*)d_in[0];
    const float* mask0 = (const float*)d_in[1];
    const float* bq    = (const float*)d_in[3];
    const float* bk    = (const float*)d_in[5];
    const float* bv    = (const float*)d_in[7];
    const float* bo    = (const float*)d_in[9];
    const float* ln_g  = (const float*)d_in[10];
    const float* ln_b  = (const float*)d_in[11];
    float* out = (float*)d_out;

    __half *pqh, *pkh, *pvh, *pxh, *pch;
    float  *phf;
    cudaGetSymbolAddress((void**)&pqh, g_qh);
    cudaGetSymbolAddress((void**)&pkh, g_kh);
    cudaGetSymbolAddress((void**)&pvh, g_vh);
    cudaGetSymbolAddress((void**)&pxh, g_xh);
    cudaGetSymbolAddress((void**)&pch, g_ctxh);
    cudaGetSymbolAddress((void**)&phf, g_hf);

    cudaFuncSetAttribute(gemm_fp16, cudaFuncAttributeMaxDynamicSharedMemorySize,
                         GEMM_SMEM);

    const float qscale = 0.28867513459481287f;  // 1/sqrt(12)

    cvt_weights<<<4 * WELTS / 4 / 256, 256>>>((const float*)d_in[2],
                                              (const float*)d_in[4],
                                              (const float*)d_in[6],
                                              (const float*)d_in[8]);
    cvt_x<<<NROWS * DD / 4 / 256, 256>>>(x);

    // Fused QKV: fp16 outputs
    GemmArgs qkv;
    qkv.plane[0] = 0; qkv.plane[1] = 1; qkv.plane[2] = 2;
    qkv.bias[0] = bq; qkv.bias[1] = bk; qkv.bias[2] = bv;
    qkv.out[0] = pqh; qkv.out[1] = pkh; qkv.out[2] = pvh;
    qkv.scale[0] = qscale; qkv.scale[1] = 1.f; qkv.scale[2] = 1.f;
    qkv.res = nullptr;
    qkv.out_half = 1;
    dim3 qkv_grid(3 * DD / BN, NROWS / BM);     // (9, 2048)
    gemm_fp16<<<qkv_grid, 256, GEMM_SMEM>>>(pxh, qkv);

    band_attn<<<BATCH * (SEQ / TS), 256>>>(mask0);

    // Output projection + residual -> fp32 h
    GemmArgs og;
    og.plane[0] = 3; og.plane[1] = 3; og.plane[2] = 3;
    og.bias[0] = bo; og.bias[1] = bo; og.bias[2] = bo;
    og.out[0] = phf; og.out[1] = phf; og.out[2] = phf;
    og.scale[0] = 1.f; og.scale[1] = 1.f; og.scale[2] = 1.f;
    og.res = x;
    og.out_half = 0;
    dim3 o_grid(DD / BN, NROWS / BM);           // (3, 2048)
    gemm_fp16<<<o_grid, 256, GEMM_SMEM>>>(pch, og);

    layernorm<<<NROWS / 8, 256>>>(ln_g, ln_b, out);
}